// round 8
// baseline (speedup 1.0000x reference)
#include <cuda_runtime.h>
#include <cuda_bf16.h>
#include <stdint.h>

#define KTOT 1024
#define DIM  64
#define HW   4096
#define QELEMS 4194304
#define DELTA 2.5e-3f
#define CAPR 8
#define INF __int_as_float(0x7f800000)

// dynamic smem offsets (bytes)
#define XS_OFF 0        // f32 xs[64][64]               16384
#define B_OFF  16384    // bf16 B[256][72] padded       36864
#define CN_OFF 53248    // f32 cn[256]                   1024
#define CD_OFF 54272    // u16 cdL[256][16]              8192
#define XN_OFF 62464    // f32 xn[64]                     256
#define RM_OFF 62720    // u64 rmn[64][2]                1024
#define SI_OFF 63744    // i32 sid[64]                    256
#define LR_OFF 64000    // f32 lred[256]                 1024
#define SMEM_BYTES 65024

__device__ float g_cnorm[KTOT];
__device__ __align__(16) __nv_bfloat16 g_cbb[KTOT*DIM];

__global__ void vq_prep(const float* __restrict__ cb, float* __restrict__ loss_ptr){
    int k = blockIdx.x*256 + threadIdx.x;
    if (k==0) *loss_ptr = 0.0f;
    if (k < KTOT){
        float s = 0.0f;
        #pragma unroll
        for (int d=0; d<DIM; ++d){
            float c = cb[k*DIM+d];
            g_cbb[k*DIM+d] = __float2bfloat16(c);
            s = __fadd_rn(s, __fmul_rn(c,c));
        }
        g_cnorm[k] = s;
    }
}

__device__ __forceinline__ uint32_t packbf(float lo, float hi){
    __nv_bfloat162 h = __floats2bfloat162_rn(lo, hi);
    return *(uint32_t*)&h;
}
__device__ __forceinline__ uint32_t f2o(float f){
    uint32_t u = __float_as_uint(f);
    return (u & 0x80000000u) ? ~u : (u | 0x80000000u);
}
#define HMMA(acc,a,b0,b1) asm volatile( \
    "mma.sync.aligned.m16n8k16.row.col.f32.bf16.bf16.f32 " \
    "{%0,%1,%2,%3}, {%4,%5,%6,%7}, {%8,%9}, {%0,%1,%2,%3};" \
    : "+f"((acc)[0]),"+f"((acc)[1]),"+f"((acc)[2]),"+f"((acc)[3]) \
    : "r"((a)[0]),"r"((a)[1]),"r"((a)[2]),"r"((a)[3]), "r"(b0),"r"(b1))

// exact R1-numerics score for row rw (smem xs [d][64]) vs codebook row k
__device__ __forceinline__ float exact_score(const float* xs, const float* cb,
                                             int rw, int k, float xnv){
    const float4* cr = (const float4*)(cb + k*DIM);
    float dot = 0.0f;
    #pragma unroll
    for (int q=0; q<16; ++q){
        float4 c = __ldg(cr+q);
        int d0 = q*4;
        dot = fmaf(xs[d0*64+rw],     c.x, dot);
        dot = fmaf(xs[(d0+1)*64+rw], c.y, dot);
        dot = fmaf(xs[(d0+2)*64+rw], c.z, dot);
        dot = fmaf(xs[(d0+3)*64+rw], c.w, dot);
    }
    return __fsub_rn(__fadd_rn(xnv, __ldg(&g_cnorm[k])), __fmul_rn(2.0f, dot));
}

__global__ void __launch_bounds__(256,3) vq_hmma_kernel(
    const float* __restrict__ x, const float* __restrict__ cb,
    float* __restrict__ out, float* __restrict__ loss_ptr)
{
    extern __shared__ char smc[];
    float*              xs  = (float*)(smc + XS_OFF);
    __nv_bfloat16*      Bs  = (__nv_bfloat16*)(smc + B_OFF);
    float*              cns = (float*)(smc + CN_OFF);
    uint16_t*           cdL = (uint16_t*)(smc + CD_OFF);
    float*              xns = (float*)(smc + XN_OFF);
    unsigned long long* rmn = (unsigned long long*)(smc + RM_OFF);
    int*                sid = (int*)(smc + SI_OFF);
    float*              lrd = (float*)(smc + LR_OFF);

    const int tid = threadIdx.x;
    const int b = blockIdx.x>>6, h = blockIdx.x&63;

    // ---- load x tile [64d][64w] (coalesced over w) ----
    {
        int w2 = tid&63, d0 = tid>>6;
        const float* xb = x + (size_t)b*DIM*HW + (size_t)h*64 + w2;
        #pragma unroll
        for (int i=0;i<16;i++){ int d = d0*16+i; xs[d*64+w2] = xb[(size_t)d*HW]; }
    }
    __syncthreads();

    // ---- per-row ||x||^2 (mul/add, ascending d) ----
    if (tid<64){
        float s=0.0f;
        #pragma unroll
        for (int d=0; d<DIM; ++d){ float v=xs[d*64+tid]; s=__fadd_rn(s,__fmul_rn(v,v)); }
        xns[tid]=s;
    }

    const int lane = tid&31, w = tid>>5;
    const int g = lane>>2, tg = lane&3;
    const int mbase = (w&3)*16, nh = w>>2;   // 4 m-quarters x 2 n-halves
    const int R0 = mbase+g, R1 = R0+8;

    // ---- A fragments (one m16 tile per warp, m16n8k16 row-major) ----
    uint32_t afr[4][4];
    #pragma unroll
    for (int ks=0; ks<4; ++ks){
        int c0 = ks*16 + 2*tg, c2 = c0 + 8;
        afr[ks][0] = packbf(xs[c0*64+R0], xs[(c0+1)*64+R0]);
        afr[ks][1] = packbf(xs[c0*64+R1], xs[(c0+1)*64+R1]);
        afr[ks][2] = packbf(xs[c2*64+R0], xs[(c2+1)*64+R0]);
        afr[ks][3] = packbf(xs[c2*64+R1], xs[(c2+1)*64+R1]);
    }

    float rm0 = INF, rm1 = INF;
    int c0cnt = 0, c1cnt = 0;

    for (int ch=0; ch<4; ++ch){
        // ---- stage B chunk (256k x 64d bf16 = 2048 uint4) + cn ----
        {
            const uint4* src = ((const uint4*)g_cbb) + ch*2048;
            #pragma unroll
            for (int j=tid; j<2048; j+=256){
                int row=j>>3, part=j&7;
                *(uint4*)(Bs + row*72 + part*8) = src[j];
            }
            cns[tid] = g_cnorm[ch*256+tid];
        }
        __syncthreads();

        #pragma unroll 1
        for (int it=0; it<4; ++it){
            int n0 = nh*128 + it*32;                  // 4 n8 tiles: n0+8t
            float acc[4][4];
            #pragma unroll
            for (int t=0;t<4;++t){ acc[t][0]=0;acc[t][1]=0;acc[t][2]=0;acc[t][3]=0; }

            #pragma unroll
            for (int ks=0; ks<4; ++ks){
                uint32_t bf[4][2];
                #pragma unroll
                for (int t=0;t<4;++t){
                    const __nv_bfloat16* bp = Bs + (n0+8*t+g)*72 + ks*16 + 2*tg;
                    bf[t][0] = *(const uint32_t*)bp;
                    bf[t][1] = *(const uint32_t*)(bp+8);
                }
                #pragma unroll
                for (int t=0;t<4;++t) HMMA(acc[t], afr[ks], bf[t][0], bf[t][1]);
            }

            float s[16];
            #pragma unroll
            for (int t=0;t<4;++t){
                float2 cn2 = *(const float2*)&cns[n0 + 8*t + 2*tg];
                s[t*4+0] = fmaf(-2.0f, acc[t][0], cn2.x);
                s[t*4+1] = fmaf(-2.0f, acc[t][1], cn2.y);
                s[t*4+2] = fmaf(-2.0f, acc[t][2], cn2.x);
                s[t*4+3] = fmaf(-2.0f, acc[t][3], cn2.y);
            }
            float im0 = fminf(fminf(s[0],s[1]),  fminf(s[4],s[5]));
            im0 = fminf(im0, fminf(fminf(s[8],s[9]),  fminf(s[12],s[13])));
            float im1 = fminf(fminf(s[2],s[3]),  fminf(s[6],s[7]));
            im1 = fminf(im1, fminf(fminf(s[10],s[11]),fminf(s[14],s[15])));

            bool hit = (im0 < rm0 + DELTA) | (im1 < rm1 + DELTA);
            rm0 = fminf(rm0, im0);
            rm1 = fminf(rm1, im1);
            if (__any_sync(0xffffffffu, hit)){
                float t0 = rm0 + DELTA, t1 = rm1 + DELTA;
                int kb = ch*256 + n0 + 2*tg;
                #pragma unroll
                for (int t=0;t<4;++t){
                    #pragma unroll
                    for (int e=0;e<2;++e){
                        if (s[t*4+e] < t0){
                            if (c0cnt < CAPR) cdL[tid*16 + c0cnt] = (uint16_t)(kb + 8*t + e);
                            c0cnt++;
                        }
                        if (s[t*4+2+e] < t1){
                            if (c1cnt < CAPR) cdL[tid*16 + 8 + c1cnt] = (uint16_t)(kb + 8*t + e);
                            c1cnt++;
                        }
                    }
                }
            }
        }
        __syncthreads();   // B consumed before next chunk overwrite
        // share running min across the quad (lanes tg=0..3 cover same rows)
        rm0 = fminf(rm0, __shfl_xor_sync(0xffffffffu, rm0, 1));
        rm0 = fminf(rm0, __shfl_xor_sync(0xffffffffu, rm0, 2));
        rm1 = fminf(rm1, __shfl_xor_sync(0xffffffffu, rm1, 1));
        rm1 = fminf(rm1, __shfl_xor_sync(0xffffffffu, rm1, 2));
    }

    // ---- per-lane exact rescore (R1 numerics), packed (score|k) min ----
    unsigned long long best0 = ~0ull, best1 = ~0ull;
    float xn0 = xns[R0], xn1 = xns[R1];

    if (c0cnt <= CAPR){
        for (int i=0; i<c0cnt; ++i){
            int k = cdL[tid*16+i];
            float sc = exact_score(xs, cb, R0, k, xn0);
            unsigned long long p = ((unsigned long long)f2o(sc)<<32) | (unsigned)k;
            if (p < best0) best0 = p;
        }
    } else {
        #pragma unroll 1
        for (int ch2=0; ch2<4; ++ch2)
            for (int j=0; j<16; ++j)
                #pragma unroll
                for (int e=0;e<2;++e){
                    int k = ch2*256 + nh*128 + j*8 + 2*tg + e;
                    float sc = exact_score(xs, cb, R0, k, xn0);
                    unsigned long long p = ((unsigned long long)f2o(sc)<<32) | (unsigned)k;
                    if (p < best0) best0 = p;
                }
    }
    if (c1cnt <= CAPR){
        for (int i=0; i<c1cnt; ++i){
            int k = cdL[tid*16+8+i];
            float sc = exact_score(xs, cb, R1, k, xn1);
            unsigned long long p = ((unsigned long long)f2o(sc)<<32) | (unsigned)k;
            if (p < best1) best1 = p;
        }
    } else {
        #pragma unroll 1
        for (int ch2=0; ch2<4; ++ch2)
            for (int j=0; j<16; ++j)
                #pragma unroll
                for (int e=0;e<2;++e){
                    int k = ch2*256 + nh*128 + j*8 + 2*tg + e;
                    float sc = exact_score(xs, cb, R1, k, xn1);
                    unsigned long long p = ((unsigned long long)f2o(sc)<<32) | (unsigned)k;
                    if (p < best1) best1 = p;
                }
    }

    // quad reduce, then per-(row, n-half) smem cell
    {
        unsigned long long v = best0, o;
        o = __shfl_xor_sync(0xffffffffu, v, 1); if (o<v) v=o;
        o = __shfl_xor_sync(0xffffffffu, v, 2); if (o<v) v=o;
        if (tg==0) rmn[R0*2 + nh] = v;
        v = best1;
        o = __shfl_xor_sync(0xffffffffu, v, 1); if (o<v) v=o;
        o = __shfl_xor_sync(0xffffffffu, v, 2); if (o<v) v=o;
        if (tg==0) rmn[R1*2 + nh] = v;
    }
    __syncthreads();
    if (tid<64){
        unsigned long long a = rmn[tid*2], c2 = rmn[tid*2+1];
        sid[tid] = (int)((a<c2?a:c2) & 0x3FFull);
    }
    __syncthreads();

    // ---- straight-through output + loss (R1 elementwise rounding) ----
    float lsum = 0.0f;
    {
        int w2 = tid&63, d0 = tid>>6;
        int k = sid[w2];
        const float* cr = cb + k*DIM;
        float* ob = out + (size_t)b*DIM*HW + (size_t)h*64 + w2;
        #pragma unroll
        for (int i=0;i<16;i++){
            int d = d0*16+i;
            float q = __ldg(cr+d), xv = xs[d*64+w2];
            float df = __fsub_rn(q, xv);
            lsum = __fadd_rn(lsum, __fmul_rn(df, df));
            ob[(size_t)d*HW] = __fadd_rn(xv, df);
        }
    }
    lrd[tid] = lsum;
    __syncthreads();
    #pragma unroll
    for (int s2=128; s2>0; s2>>=1){
        if (tid<s2) lrd[tid] = __fadd_rn(lrd[tid], lrd[tid+s2]);
        __syncthreads();
    }
    if (tid==0) atomicAdd(loss_ptr, lrd[0] * (1.25f/(float)QELEMS));
}

extern "C" void kernel_launch(void* const* d_in, const int* in_sizes, int n_in,
                              void* d_out, int out_size) {
    const float* x  = (const float*)d_in[0];
    const float* cb = (const float*)d_in[1];
    float* out = (float*)d_out;
    float* loss_ptr = out + (out_size - 1);

    cudaFuncSetAttribute(vq_hmma_kernel, cudaFuncAttributeMaxDynamicSharedMemorySize, SMEM_BYTES);
    vq_prep<<<4, 256>>>(cb, loss_ptr);
    vq_hmma_kernel<<<1024, 256, SMEM_BYTES>>>(x, cb, out, loss_ptr);
}

// round 9
// speedup vs baseline: 2.8775x; 2.8775x over previous
#include <cuda_runtime.h>
#include <cuda_bf16.h>
#include <stdint.h>

#define KTOT 1024
#define DIM  64
#define HW   4096
#define QELEMS 4194304
#define DELTA 2.5e-3f
#define INF __int_as_float(0x7f800000)

// dynamic smem offsets (bytes)
#define XS_OFF 0        // f32 xs[64][64]               16384
#define B_OFF  16384    // bf16 B[256][72] padded       36864
#define CN_OFF 53248    // f32 cn[256]                   1024
#define XN_OFF 54272    // f32 xn[64]                     256
#define TH_OFF 54528    // f32 thp[64][2]                 512
#define TR_OFF 55040    // f32 thr[64]                    256
#define BM_OFF 55296    // u64 brm[64]                    512
#define SI_OFF 55808    // i32 sid[64]                    256
#define LR_OFF 56064    // f32 lred[256]                 1024
#define SMEM_BYTES 57088

__device__ float g_cnorm[KTOT];
__device__ __align__(16) __nv_bfloat16 g_cbb[KTOT*DIM];

__global__ void vq_prep(const float* __restrict__ cb, float* __restrict__ loss_ptr){
    int k = blockIdx.x*256 + threadIdx.x;
    if (k==0) *loss_ptr = 0.0f;
    if (k < KTOT){
        float s = 0.0f;
        #pragma unroll
        for (int d=0; d<DIM; ++d){
            float c = cb[k*DIM+d];
            g_cbb[k*DIM+d] = __float2bfloat16(c);
            s = __fadd_rn(s, __fmul_rn(c,c));
        }
        g_cnorm[k] = s;
    }
}

__device__ __forceinline__ uint32_t packbf(float lo, float hi){
    __nv_bfloat162 h = __floats2bfloat162_rn(lo, hi);
    return *(uint32_t*)&h;
}
__device__ __forceinline__ uint32_t f2o(float f){
    uint32_t u = __float_as_uint(f);
    return (u & 0x80000000u) ? ~u : (u | 0x80000000u);
}
#define HMMA(acc,a,b0,b1) asm volatile( \
    "mma.sync.aligned.m16n8k16.row.col.f32.bf16.bf16.f32 " \
    "{%0,%1,%2,%3}, {%4,%5,%6,%7}, {%8,%9}, {%0,%1,%2,%3};" \
    : "+f"((acc)[0]),"+f"((acc)[1]),"+f"((acc)[2]),"+f"((acc)[3]) \
    : "r"((a)[0]),"r"((a)[1]),"r"((a)[2]),"r"((a)[3]), "r"(b0),"r"(b1))

// exact R1-numerics score for row rw (smem xs [d][64]) vs codebook row k
__device__ __forceinline__ float exact_score(const float* xs, const float* cb,
                                             int rw, int k, float xnv){
    const float4* cr = (const float4*)(cb + k*DIM);
    float dot = 0.0f;
    #pragma unroll
    for (int q=0; q<16; ++q){
        float4 c = __ldg(cr+q);
        int d0 = q*4;
        dot = fmaf(xs[d0*64+rw],     c.x, dot);
        dot = fmaf(xs[(d0+1)*64+rw], c.y, dot);
        dot = fmaf(xs[(d0+2)*64+rw], c.z, dot);
        dot = fmaf(xs[(d0+3)*64+rw], c.w, dot);
    }
    return __fsub_rn(__fadd_rn(xnv, __ldg(&g_cnorm[k])), __fmul_rn(2.0f, dot));
}

__global__ void __launch_bounds__(256,3) vq_hmma_kernel(
    const float* __restrict__ x, const float* __restrict__ cb,
    float* __restrict__ out, float* __restrict__ loss_ptr)
{
    extern __shared__ char smc[];
    float*              xs  = (float*)(smc + XS_OFF);
    __nv_bfloat16*      Bs  = (__nv_bfloat16*)(smc + B_OFF);
    float*              cns = (float*)(smc + CN_OFF);
    float*              xns = (float*)(smc + XN_OFF);
    float*              thp = (float*)(smc + TH_OFF);
    float*              thrS= (float*)(smc + TR_OFF);
    unsigned long long* brm = (unsigned long long*)(smc + BM_OFF);
    int*                sid = (int*)(smc + SI_OFF);
    float*              lrd = (float*)(smc + LR_OFF);

    const int tid = threadIdx.x;
    const int b = blockIdx.x>>6, h = blockIdx.x&63;

    // ---- load x tile [64d][64w] (coalesced over w) ----
    {
        int w2 = tid&63, d0 = tid>>6;
        const float* xb = x + (size_t)b*DIM*HW + (size_t)h*64 + w2;
        #pragma unroll
        for (int i=0;i<16;i++){ int d = d0*16+i; xs[d*64+w2] = xb[(size_t)d*HW]; }
    }
    __syncthreads();

    // ---- per-row ||x||^2 (mul/add, ascending d) ----
    if (tid<64){
        float s=0.0f;
        #pragma unroll
        for (int d=0; d<DIM; ++d){ float v=xs[d*64+tid]; s=__fadd_rn(s,__fmul_rn(v,v)); }
        xns[tid]=s;
    }

    const int lane = tid&31, w = tid>>5;
    const int g = lane>>2, tg = lane&3;
    const int mbase = (w&3)*16, nh = w>>2;   // 4 m-quarters x 2 n-halves
    const int R0 = mbase+g, R1 = R0+8;

    // ---- A fragments (one m16 tile per warp, m16n8k16 row-major) ----
    uint32_t afr[4][4];
    #pragma unroll
    for (int ks=0; ks<4; ++ks){
        int c0 = ks*16 + 2*tg, c2 = c0 + 8;
        afr[ks][0] = packbf(xs[c0*64+R0], xs[(c0+1)*64+R0]);
        afr[ks][1] = packbf(xs[c0*64+R1], xs[(c0+1)*64+R1]);
        afr[ks][2] = packbf(xs[c2*64+R0], xs[(c2+1)*64+R0]);
        afr[ks][3] = packbf(xs[c2*64+R1], xs[(c2+1)*64+R1]);
    }

    float rm0 = INF, rm1 = INF;
    float thr0 = 0.0f, thr1 = 0.0f, xn0 = 0.0f, xn1 = 0.0f;

    #pragma unroll 1
    for (int pass=0; pass<2; ++pass){
        if (pass==1){
            // reduce per-lane mins -> global per-row threshold
            rm0 = fminf(rm0, __shfl_xor_sync(0xffffffffu, rm0, 1));
            rm0 = fminf(rm0, __shfl_xor_sync(0xffffffffu, rm0, 2));
            rm1 = fminf(rm1, __shfl_xor_sync(0xffffffffu, rm1, 1));
            rm1 = fminf(rm1, __shfl_xor_sync(0xffffffffu, rm1, 2));
            if (tg==0){ thp[R0*2+nh] = rm0; thp[R1*2+nh] = rm1; }
            if (tid<64) brm[tid] = ~0ull;
            __syncthreads();
            if (tid<64) thrS[tid] = fminf(thp[tid*2], thp[tid*2+1]) + DELTA;
            __syncthreads();
            thr0 = thrS[R0]; thr1 = thrS[R1];
            xn0 = xns[R0];   xn1 = xns[R1];
        }

        #pragma unroll 1
        for (int ch=0; ch<4; ++ch){
            // ---- stage B chunk (256k x 64d bf16 = 2048 uint4) + cn ----
            {
                const uint4* src = ((const uint4*)g_cbb) + ch*2048;
                #pragma unroll
                for (int j=tid; j<2048; j+=256){
                    int row=j>>3, part=j&7;
                    *(uint4*)(Bs + row*72 + part*8) = src[j];
                }
                cns[tid] = g_cnorm[ch*256+tid];
            }
            __syncthreads();

            #pragma unroll 1
            for (int it=0; it<4; ++it){
                int n0 = nh*128 + it*32;                  // 4 n8 tiles
                float acc[4][4];
                #pragma unroll
                for (int t=0;t<4;++t){ acc[t][0]=0;acc[t][1]=0;acc[t][2]=0;acc[t][3]=0; }

                #pragma unroll
                for (int ks=0; ks<4; ++ks){
                    uint32_t bf[4][2];
                    #pragma unroll
                    for (int t=0;t<4;++t){
                        const __nv_bfloat16* bp = Bs + (n0+8*t+g)*72 + ks*16 + 2*tg;
                        bf[t][0] = *(const uint32_t*)bp;
                        bf[t][1] = *(const uint32_t*)(bp+8);
                    }
                    #pragma unroll
                    for (int t=0;t<4;++t) HMMA(acc[t], afr[ks], bf[t][0], bf[t][1]);
                }

                float s[16];
                #pragma unroll
                for (int t=0;t<4;++t){
                    float2 cn2 = *(const float2*)&cns[n0 + 8*t + 2*tg];
                    s[t*4+0] = fmaf(-2.0f, acc[t][0], cn2.x);
                    s[t*4+1] = fmaf(-2.0f, acc[t][1], cn2.y);
                    s[t*4+2] = fmaf(-2.0f, acc[t][2], cn2.x);
                    s[t*4+3] = fmaf(-2.0f, acc[t][3], cn2.y);
                }
                float im0 = fminf(fminf(s[0],s[1]),  fminf(s[4],s[5]));
                im0 = fminf(im0, fminf(fminf(s[8],s[9]),  fminf(s[12],s[13])));
                float im1 = fminf(fminf(s[2],s[3]),  fminf(s[6],s[7]));
                im1 = fminf(im1, fminf(fminf(s[10],s[11]),fminf(s[14],s[15])));

                if (pass==0){
                    rm0 = fminf(rm0, im0);
                    rm1 = fminf(rm1, im1);
                } else {
                    bool hit = (im0 < thr0) | (im1 < thr1);
                    if (__any_sync(0xffffffffu, hit)){
                        #pragma unroll
                        for (int t=0;t<4;++t){
                            #pragma unroll
                            for (int e=0;e<2;++e){
                                int k = ch*256 + n0 + 8*t + 2*tg + e;
                                if (s[t*4+e] < thr0){
                                    float sc = exact_score(xs, cb, R0, k, xn0);
                                    unsigned long long p =
                                        ((unsigned long long)f2o(sc)<<32) | (unsigned)k;
                                    atomicMin(&brm[R0], p);
                                }
                                if (s[t*4+2+e] < thr1){
                                    float sc = exact_score(xs, cb, R1, k, xn1);
                                    unsigned long long p =
                                        ((unsigned long long)f2o(sc)<<32) | (unsigned)k;
                                    atomicMin(&brm[R1], p);
                                }
                            }
                        }
                    }
                }
            }
            __syncthreads();   // B consumed before next chunk overwrite
        }
    }

    if (tid<64) sid[tid] = (int)(brm[tid] & 0x3FFull);
    __syncthreads();

    // ---- straight-through output + loss (R1 elementwise rounding) ----
    float lsum = 0.0f;
    {
        int w2 = tid&63, d0 = tid>>6;
        int k = sid[w2];
        const float* cr = cb + k*DIM;
        float* ob = out + (size_t)b*DIM*HW + (size_t)h*64 + w2;
        #pragma unroll
        for (int i=0;i<16;i++){
            int d = d0*16+i;
            float q = __ldg(cr+d), xv = xs[d*64+w2];
            float df = __fsub_rn(q, xv);
            lsum = __fadd_rn(lsum, __fmul_rn(df, df));
            ob[(size_t)d*HW] = __fadd_rn(xv, df);
        }
    }
    lrd[tid] = lsum;
    __syncthreads();
    #pragma unroll
    for (int s2=128; s2>0; s2>>=1){
        if (tid<s2) lrd[tid] = __fadd_rn(lrd[tid], lrd[tid+s2]);
        __syncthreads();
    }
    if (tid==0) atomicAdd(loss_ptr, lrd[0] * (1.25f/(float)QELEMS));
}

extern "C" void kernel_launch(void* const* d_in, const int* in_sizes, int n_in,
                              void* d_out, int out_size) {
    const float* x  = (const float*)d_in[0];
    const float* cb = (const float*)d_in[1];
    float* out = (float*)d_out;
    float* loss_ptr = out + (out_size - 1);

    cudaFuncSetAttribute(vq_hmma_kernel, cudaFuncAttributeMaxDynamicSharedMemorySize, SMEM_BYTES);
    vq_prep<<<4, 256>>>(cb, loss_ptr);
    vq_hmma_kernel<<<1024, 256, SMEM_BYTES>>>(x, cb, out, loss_ptr);
}

// round 11
// speedup vs baseline: 2.9739x; 1.0335x over previous
#include <cuda_runtime.h>
#include <cuda_bf16.h>
#include <stdint.h>

#define KTOT 1024
#define DIM  64
#define HW   4096
#define QELEMS 4194304
#define DELTA 2.5e-3f
#define INF __int_as_float(0x7f800000)

// dynamic smem offsets (bytes)
#define XS_OFF 0        // f32 xs[64][64]               16384
#define B_OFF  16384    // bf16 B[256][72] padded       36864
#define CN_OFF 53248    // f32 cn[256]                   1024
#define XN_OFF 54272    // f32 xn[64]                     256
#define TH_OFF 54528    // f32 thp[64][2]                 512
#define TR_OFF 55040    // f32 thr[64]                    256
#define BM_OFF 55296    // u64 brm[64]                    512
#define SI_OFF 55808    // i32 sid[64]                    256
#define LR_OFF 56064    // f32 lred[256]                 1024
#define SMEM_BYTES 57088

__device__ float g_cnorm[KTOT];
__device__ __align__(16) __nv_bfloat16 g_cbb[KTOT*DIM];

__global__ void vq_prep(const float* __restrict__ cb, float* __restrict__ loss_ptr){
    int k = blockIdx.x*256 + threadIdx.x;
    if (k==0) *loss_ptr = 0.0f;
    if (k < KTOT){
        float s = 0.0f;
        #pragma unroll
        for (int d=0; d<DIM; ++d){
            float c = cb[k*DIM+d];
            g_cbb[k*DIM+d] = __float2bfloat16(c);
            s = __fadd_rn(s, __fmul_rn(c,c));
        }
        g_cnorm[k] = s;
    }
}

__device__ __forceinline__ uint32_t packbf(float lo, float hi){
    __nv_bfloat162 h = __floats2bfloat162_rn(lo, hi);
    return *(uint32_t*)&h;
}
__device__ __forceinline__ uint32_t f2o(float f){
    uint32_t u = __float_as_uint(f);
    return (u & 0x80000000u) ? ~u : (u | 0x80000000u);
}
__device__ __forceinline__ uint32_t s2u(const void* p){
    uint32_t a; asm("{ .reg .u64 t; cvta.to.shared.u64 t, %1; cvt.u32.u64 %0, t; }":"=r"(a):"l"(p)); return a;
}
#define HMMA(acc,a,b0,b1) asm volatile( \
    "mma.sync.aligned.m16n8k16.row.col.f32.bf16.bf16.f32 " \
    "{%0,%1,%2,%3}, {%4,%5,%6,%7}, {%8,%9}, {%0,%1,%2,%3};" \
    : "+f"((acc)[0]),"+f"((acc)[1]),"+f"((acc)[2]),"+f"((acc)[3]) \
    : "r"((a)[0]),"r"((a)[1]),"r"((a)[2]),"r"((a)[3]), "r"(b0),"r"(b1))
#define LDSM4(r,a) asm volatile( \
    "ldmatrix.sync.aligned.m8n8.x4.shared.b16 {%0,%1,%2,%3}, [%4];" \
    : "=r"((r)[0]),"=r"((r)[1]),"=r"((r)[2]),"=r"((r)[3]) : "r"(a))
#define CPASYNC16(dst,src) asm volatile( \
    "cp.async.cg.shared.global [%0], [%1], 16;" :: "r"(dst), "l"(src))

// exact R1-numerics score for row rw (smem xs [d][64]) vs codebook row k
__device__ __forceinline__ float exact_score(const float* xs, const float* cb,
                                             int rw, int k, float xnv){
    const float4* cr = (const float4*)(cb + k*DIM);
    float dot = 0.0f;
    #pragma unroll
    for (int q=0; q<16; ++q){
        float4 c = __ldg(cr+q);
        int d0 = q*4;
        dot = fmaf(xs[d0*64+rw],     c.x, dot);
        dot = fmaf(xs[(d0+1)*64+rw], c.y, dot);
        dot = fmaf(xs[(d0+2)*64+rw], c.z, dot);
        dot = fmaf(xs[(d0+3)*64+rw], c.w, dot);
    }
    return __fsub_rn(__fadd_rn(xnv, __ldg(&g_cnorm[k])), __fmul_rn(2.0f, dot));
}

__global__ void __launch_bounds__(256,3) vq_hmma_kernel(
    const float* __restrict__ x, const float* __restrict__ cb,
    float* __restrict__ out, float* __restrict__ loss_ptr)
{
    extern __shared__ char smc[];
    float*              xs  = (float*)(smc + XS_OFF);
    float*              cns = (float*)(smc + CN_OFF);
    float*              xns = (float*)(smc + XN_OFF);
    float*              thp = (float*)(smc + TH_OFF);
    float*              thrS= (float*)(smc + TR_OFF);
    unsigned long long* brm = (unsigned long long*)(smc + BM_OFF);
    int*                sid = (int*)(smc + SI_OFF);
    float*              lrd = (float*)(smc + LR_OFF);
    const uint32_t Bu  = s2u(smc + B_OFF);
    const uint32_t CNu = s2u(smc + CN_OFF);

    const int tid = threadIdx.x;
    const int b = blockIdx.x>>6, h = blockIdx.x&63;

    // ---- load x tile [64d][64w] (coalesced over w) ----
    {
        int w2 = tid&63, d0 = tid>>6;
        const float* xb = x + (size_t)b*DIM*HW + (size_t)h*64 + w2;
        #pragma unroll
        for (int i=0;i<16;i++){ int d = d0*16+i; xs[d*64+w2] = xb[(size_t)d*HW]; }
    }
    __syncthreads();

    // ---- per-row ||x||^2 (mul/add, ascending d) ----
    if (tid<64){
        float s=0.0f;
        #pragma unroll
        for (int d=0; d<DIM; ++d){ float v=xs[d*64+tid]; s=__fadd_rn(s,__fmul_rn(v,v)); }
        xns[tid]=s;
    }

    const int lane = tid&31, w = tid>>5;
    const int g = lane>>2, tg = lane&3;
    const int mbase = (w&3)*16, nh = w>>2;   // 4 m-quarters x 2 n-halves
    const int R0 = mbase+g, R1 = R0+8;
    // ldmatrix per-lane address: row (lane&7), k-block (lane>>3)*16 bytes
    const uint32_t lds_base = Bu + (uint32_t)(lane&7)*144u + (uint32_t)(lane>>3)*16u;

    // ---- A fragments (one m16 tile per warp, m16n8k16 row-major) ----
    uint32_t afr[4][4];
    #pragma unroll
    for (int ks=0; ks<4; ++ks){
        int c0 = ks*16 + 2*tg, c2 = c0 + 8;
        afr[ks][0] = packbf(xs[c0*64+R0], xs[(c0+1)*64+R0]);
        afr[ks][1] = packbf(xs[c0*64+R1], xs[(c0+1)*64+R1]);
        afr[ks][2] = packbf(xs[c2*64+R0], xs[(c2+1)*64+R0]);
        afr[ks][3] = packbf(xs[c2*64+R1], xs[(c2+1)*64+R1]);
    }

    float rm0 = INF, rm1 = INF;
    float thr0 = 0.0f, thr1 = 0.0f, xn0 = 0.0f, xn1 = 0.0f;

    #pragma unroll 1
    for (int pass=0; pass<2; ++pass){
        if (pass==1){
            // reduce per-lane mins -> global per-row threshold
            rm0 = fminf(rm0, __shfl_xor_sync(0xffffffffu, rm0, 1));
            rm0 = fminf(rm0, __shfl_xor_sync(0xffffffffu, rm0, 2));
            rm1 = fminf(rm1, __shfl_xor_sync(0xffffffffu, rm1, 1));
            rm1 = fminf(rm1, __shfl_xor_sync(0xffffffffu, rm1, 2));
            if (tg==0){ thp[R0*2+nh] = rm0; thp[R1*2+nh] = rm1; }
            if (tid<64) brm[tid] = ~0ull;
            __syncthreads();
            if (tid<64) thrS[tid] = fminf(thp[tid*2], thp[tid*2+1]) + DELTA;
            __syncthreads();
            thr0 = thrS[R0]; thr1 = thrS[R1];
            xn0 = xns[R0];   xn1 = xns[R1];
        }

        #pragma unroll 1
        for (int c=0; c<4; ++c){
            // pass 1: chunks 0..3; pass 2: 3..0 (chunk 3 still resident -> skip)
            const int ch = (pass==0) ? c : (3-c);
            if (!(pass==1 && c==0)){
                // ---- stage B chunk via cp.async (256k x 128B) + cn ----
                {
                    const uint4* src = ((const uint4*)g_cbb) + ch*2048;
                    #pragma unroll
                    for (int j=tid; j<2048; j+=256){
                        uint32_t dst = Bu + (uint32_t)(j>>3)*144u + (uint32_t)(j&7)*16u;
                        CPASYNC16(dst, src + j);
                    }
                    if (tid<64)
                        CPASYNC16(CNu + tid*16u, (const uint4*)(g_cnorm + ch*256) + tid);
                    asm volatile("cp.async.commit_group;" ::: "memory");
                    asm volatile("cp.async.wait_group 0;" ::: "memory");
                }
                __syncthreads();
            }

            #pragma unroll 1
            for (int it=0; it<4; ++it){
                int n0 = nh*128 + it*32;                  // 4 n8 tiles
                float acc[4][4];
                #pragma unroll
                for (int t=0;t<4;++t){ acc[t][0]=0;acc[t][1]=0;acc[t][2]=0;acc[t][3]=0; }

                #pragma unroll
                for (int pr=0; pr<2; ++pr){               // tile pairs (0,1),(2,3)
                    int t0 = pr*2, t1 = t0+1;
                    uint32_t f0[8], f1[8];
                    uint32_t a0 = lds_base + (uint32_t)(n0 + 8*t0)*144u;
                    uint32_t a1 = lds_base + (uint32_t)(n0 + 8*t1)*144u;
                    LDSM4(f0,   a0); LDSM4(f0+4, a0+64u);   // FIX: k=32..63 is +64B, not +128B
                    LDSM4(f1,   a1); LDSM4(f1+4, a1+64u);
                    #pragma unroll
                    for (int ks=0; ks<4; ++ks){
                        HMMA(acc[t0], afr[ks], f0[2*ks], f0[2*ks+1]);
                        HMMA(acc[t1], afr[ks], f1[2*ks], f1[2*ks+1]);
                    }
                }

                float s[16];
                #pragma unroll
                for (int t=0;t<4;++t){
                    float2 cn2 = *(const float2*)&cns[n0 + 8*t + 2*tg];
                    s[t*4+0] = fmaf(-2.0f, acc[t][0], cn2.x);
                    s[t*4+1] = fmaf(-2.0f, acc[t][1], cn2.y);
                    s[t*4+2] = fmaf(-2.0f, acc[t][2], cn2.x);
                    s[t*4+3] = fmaf(-2.0f, acc[t][3], cn2.y);
                }
                float im0 = fminf(fminf(s[0],s[1]),  fminf(s[4],s[5]));
                im0 = fminf(im0, fminf(fminf(s[8],s[9]),  fminf(s[12],s[13])));
                float im1 = fminf(fminf(s[2],s[3]),  fminf(s[6],s[7]));
                im1 = fminf(im1, fminf(fminf(s[10],s[11]),fminf(s[14],s[15])));

                if (pass==0){
                    rm0 = fminf(rm0, im0);
                    rm1 = fminf(rm1, im1);
                } else {
                    bool hit = (im0 < thr0) | (im1 < thr1);
                    if (__any_sync(0xffffffffu, hit)){
                        #pragma unroll
                        for (int t=0;t<4;++t){
                            #pragma unroll
                            for (int e=0;e<2;++e){
                                int k = ch*256 + n0 + 8*t + 2*tg + e;
                                if (s[t*4+e] < thr0){
                                    float sc = exact_score(xs, cb, R0, k, xn0);
                                    unsigned long long p =
                                        ((unsigned long long)f2o(sc)<<32) | (unsigned)k;
                                    atomicMin(&brm[R0], p);
                                }
                                if (s[t*4+2+e] < thr1){
                                    float sc = exact_score(xs, cb, R1, k, xn1);
                                    unsigned long long p =
                                        ((unsigned long long)f2o(sc)<<32) | (unsigned)k;
                                    atomicMin(&brm[R1], p);
                                }
                            }
                        }
                    }
                }
            }
            __syncthreads();   // B consumed before next chunk overwrite
        }
    }

    if (tid<64) sid[tid] = (int)(brm[tid] & 0x3FFull);
    __syncthreads();

    // ---- straight-through output + loss (R1 elementwise rounding) ----
    float lsum = 0.0f;
    {
        int w2 = tid&63, d0 = tid>>6;
        int k = sid[w2];
        const float* cr = cb + k*DIM;
        float* ob = out + (size_t)b*DIM*HW + (size_t)h*64 + w2;
        #pragma unroll
        for (int i=0;i<16;i++){
            int d = d0*16+i;
            float q = __ldg(cr+d), xv = xs[d*64+w2];
            float df = __fsub_rn(q, xv);
            lsum = __fadd_rn(lsum, __fmul_rn(df, df));
            ob[(size_t)d*HW] = __fadd_rn(xv, df);
        }
    }
    lrd[tid] = lsum;
    __syncthreads();
    #pragma unroll
    for (int s2=128; s2>0; s2>>=1){
        if (tid<s2) lrd[tid] = __fadd_rn(lrd[tid], lrd[tid+s2]);
        __syncthreads();
    }
    if (tid==0) atomicAdd(loss_ptr, lrd[0] * (1.25f/(float)QELEMS));
}

extern "C" void kernel_launch(void* const* d_in, const int* in_sizes, int n_in,
                              void* d_out, int out_size) {
    const float* x  = (const float*)d_in[0];
    const float* cb = (const float*)d_in[1];
    float* out = (float*)d_out;
    float* loss_ptr = out + (out_size - 1);

    cudaFuncSetAttribute(vq_hmma_kernel, cudaFuncAttributeMaxDynamicSharedMemorySize, SMEM_BYTES);
    vq_prep<<<4, 256>>>(cb, loss_ptr);
    vq_hmma_kernel<<<1024, 256, SMEM_BYTES>>>(x, cb, out, loss_ptr);
}